// round 12
// baseline (speedup 1.0000x reference)
#include <cuda_runtime.h>
#include <math.h>

#define HID   512
#define MTOT  16384             // 32*512 rows, m = b*512 + t
#define OUT_HID  16777216ull    // 32*512*1024
#define OUT_CELL 16842752ull
#define OUT_FULL 16908288

// ---------------- static device scratch (fp32 only) ----------------
__device__ __align__(16) float g_gxf[(size_t)MTOT*2048];  // fwd gates (input proj + biases)
__device__ __align__(16) float g_gxr[(size_t)MTOT*2048];  // rev gates
__device__ __align__(16) float g_y[(size_t)MTOT*1024];    // layer-0 output [m][2H]
__device__ __align__(16) float g_h[2][2][16384];          // [parity][dir][u*32+b]
__device__ unsigned g_cnt[2];
__device__ unsigned g_gen[2];

__global__ void init_state() {
    int i = blockIdx.x*256 + threadIdx.x;
    if (i < 2*2*16384) ((float*)g_h)[i] = 0.f;
    if (i < 2) { g_cnt[i] = 0u; g_gen[i] = 0u; }
}

// ---------------- fp32 SIMT GEMM: C[MTOT x 2048] = A[MTOT x K] @ W[2048 x K]^T + bi + bh ----
// Unchanged from the validated round-10 kernel.
__global__ __launch_bounds__(256) void gemm_nt(
        const float* __restrict__ Xin, int asel,
        const float* __restrict__ W,
        const float* __restrict__ bi, const float* __restrict__ bh,
        int csel, int K) {
    __shared__ __align__(16) float As[16][64];
    __shared__ __align__(16) float Bs[16][64];
    const float* A = asel ? g_y : Xin;
    float*       C = csel ? g_gxr : g_gxf;

    const int m0 = blockIdx.y*64, n0 = blockIdx.x*64;
    const int tid = threadIdx.x;
    const int lrow = tid >> 2;          // 0..63
    const int lkq  = (tid & 3) * 4;     // 0,4,8,12
    const int ty = tid >> 4, tx = tid & 15;

    float acc[4][4];
#pragma unroll
    for (int i = 0; i < 4; i++)
#pragma unroll
        for (int j = 0; j < 4; j++) acc[i][j] = 0.f;

    for (int k0 = 0; k0 < K; k0 += 16) {
        float4 av = *(const float4*)&A[(size_t)(m0 + lrow)*K + k0 + lkq];
        float4 bv = *(const float4*)&W[(size_t)(n0 + lrow)*K + k0 + lkq];
        As[lkq+0][lrow] = av.x; As[lkq+1][lrow] = av.y;
        As[lkq+2][lrow] = av.z; As[lkq+3][lrow] = av.w;
        Bs[lkq+0][lrow] = bv.x; Bs[lkq+1][lrow] = bv.y;
        Bs[lkq+2][lrow] = bv.z; Bs[lkq+3][lrow] = bv.w;
        __syncthreads();
#pragma unroll
        for (int k = 0; k < 16; k++) {
            float4 a4 = *(const float4*)&As[k][ty*4];
            float4 b4 = *(const float4*)&Bs[k][tx*4];
            float ar[4] = {a4.x, a4.y, a4.z, a4.w};
            float br[4] = {b4.x, b4.y, b4.z, b4.w};
#pragma unroll
            for (int i = 0; i < 4; i++)
#pragma unroll
                for (int j = 0; j < 4; j++) acc[i][j] += ar[i]*br[j];
        }
        __syncthreads();
    }
#pragma unroll
    for (int j = 0; j < 4; j++) {
        int n = n0 + tx*4 + j;
        float bsum = bi[n] + bh[n];
#pragma unroll
        for (int i = 0; i < 4; i++)
            C[(size_t)(m0 + ty*4 + i)*2048 + n] = acc[i][j] + bsum;
    }
}

// ---------------- persistent bidirectional LSTM layer ----------------
// Same math/indexing as the validated round-10 lstm_step, restructured as a
// persistent kernel: the s-loop moves inside, W_hh is staged into smem ONCE,
// and a per-direction software grid barrier orders the timesteps.
// 128 CTAs x 128KB dynamic smem -> 1 CTA/SM, all co-resident (128 < 148 SMs),
// so the barrier cannot deadlock.
__global__ void __launch_bounds__(256, 1) lstm_layer(
        const float* __restrict__ Whf, const float* __restrict__ Whr,
        int layer, float* __restrict__ out, int out_size) {
    extern __shared__ float sm[];
    float* sW = sm;           // [32][512]  rows: gate g (0..3) * 8 + local unit
    float* sh = sm + 16384;   // [512][32]  h_prev, [k*32 + b]

    const int dir = blockIdx.x >> 6;
    const int u0 = (blockIdx.x & 63) * 8;
    const int tid = threadIdx.x, w = tid >> 5, b = tid & 31;
    const int u = u0 + w;
    const float* Whh = dir ? Whr : Whf;
    const float* gx  = dir ? g_gxr : g_gxf;

    // stage W_hh rows for this block's 8 units (4 gates each) -- once
    for (int i = tid; i < 32*512; i += 256) {
        int ri = i >> 9, k = i & 511;
        sW[i] = Whh[(size_t)(((ri >> 3) << 9) + u0 + (ri & 7))*512 + k];
    }
    float c = 0.f;
    __syncthreads();

    for (int s = 0; s < 512; ++s) {
        const int t = dir ? (511 - s) : s;
        const int rp = s & 1, wp = rp ^ 1;

        // stage h_prev (bypass L1: other SMs wrote it)
        const float4* hsrc = (const float4*)g_h[rp][dir];
        for (int i = tid; i < 4096; i += 256)
            ((float4*)sh)[i] = __ldcg(hsrc + i);
        __syncthreads();

        const size_t gb = ((size_t)b*512 + t)*2048 + u;
        float a0 = gx[gb];
        float a1 = gx[gb + 512];
        float a2 = gx[gb + 1024];
        float a3 = gx[gb + 1536];

        const float* r0 = sW + (size_t)( w      )*512;
        const float* r1 = sW + (size_t)( 8 + w  )*512;
        const float* r2 = sW + (size_t)(16 + w  )*512;
        const float* r3 = sW + (size_t)(24 + w  )*512;
#pragma unroll 4
        for (int k = 0; k < 512; k += 4) {
            float4 w0 = *(const float4*)(r0 + k);
            float4 w1 = *(const float4*)(r1 + k);
            float4 w2 = *(const float4*)(r2 + k);
            float4 w3 = *(const float4*)(r3 + k);
            float h0 = sh[(k+0)*32 + b];
            float h1 = sh[(k+1)*32 + b];
            float h2 = sh[(k+2)*32 + b];
            float h3 = sh[(k+3)*32 + b];
            a0 += w0.x*h0 + w0.y*h1 + w0.z*h2 + w0.w*h3;
            a1 += w1.x*h0 + w1.y*h1 + w1.z*h2 + w1.w*h3;
            a2 += w2.x*h0 + w2.y*h1 + w2.z*h2 + w2.w*h3;
            a3 += w3.x*h0 + w3.y*h1 + w3.z*h2 + w3.w*h3;
        }

        float ig = 1.f / (1.f + expf(-a0));
        float fg = 1.f / (1.f + expf(-a1));
        float gg = tanhf(a2);
        float og = 1.f / (1.f + expf(-a3));
        c = fg * c + ig * gg;
        float h = og * tanhf(c);

        g_h[wp][dir][u*32 + b] = h;

        const size_t mo = ((size_t)b*512 + t)*1024 + (size_t)dir*512 + u;
        if (layer == 0) g_y[mo] = h;
        else            out[mo]  = h;

        if (s == 511 && out_size >= OUT_FULL) {
            size_t o = (size_t)(layer*2 + dir)*16384 + (size_t)b*512 + u;
            out[OUT_HID  + o] = h;
            out[OUT_CELL + o] = c;
        }

        // per-direction grid barrier (64 arrivals), generation-counted
        __threadfence();
        __syncthreads();
        if (tid == 0) {
            volatile unsigned* vg = &g_gen[dir];
            unsigned g = *vg;
            __threadfence();
            if (atomicAdd(&g_cnt[dir], 1u) == 63u) {
                atomicExch(&g_cnt[dir], 0u);
                __threadfence();
                atomicExch(&g_gen[dir], g + 1u);
            } else {
                while (*vg == g) __nanosleep(64);
            }
        }
        __syncthreads();
    }
}

// ---------------- launch ----------------
extern "C" void kernel_launch(void* const* d_in, const int* in_sizes, int n_in,
                              void* d_out, int out_size) {
    // Input-order detection via in_sizes (X is the only 8,388,608-elem input).
    int iX, iWih0f, iWhh0f, ibi0f, ibh0f, iWih0r, iWhh0r, ibi0r, ibh0r;
    int iWih1f, iWhh1f, ibi1f, ibh1f, iWih1r, iWhh1r, ibi1r, ibh1r;
    if (n_in >= 17 && in_sizes[0] != MTOT*512 && in_sizes[8] == MTOT*512) {
        // alphabetical-ASCII order
        iWhh0f = 0; iWhh0r = 1; iWhh1f = 2; iWhh1r = 3;
        iWih0f = 4; iWih0r = 5; iWih1f = 6; iWih1r = 7;
        iX = 8;
        ibh0f = 9;  ibh0r = 10; ibh1f = 11; ibh1r = 12;
        ibi0f = 13; ibi0r = 14; ibi1f = 15; ibi1r = 16;
    } else {
        // reference-signature / insertion order
        iX = 0;
        iWih0f = 1;  iWhh0f = 2;  ibi0f = 3;  ibh0f = 4;
        iWih0r = 5;  iWhh0r = 6;  ibi0r = 7;  ibh0r = 8;
        iWih1f = 9;  iWhh1f = 10; ibi1f = 11; ibh1f = 12;
        iWih1r = 13; iWhh1r = 14; ibi1r = 15; ibh1r = 16;
    }
    const float* X     = (const float*)d_in[iX];
    const float* Wih0f = (const float*)d_in[iWih0f];
    const float* Whh0f = (const float*)d_in[iWhh0f];
    const float* bi0f  = (const float*)d_in[ibi0f];
    const float* bh0f  = (const float*)d_in[ibh0f];
    const float* Wih0r = (const float*)d_in[iWih0r];
    const float* Whh0r = (const float*)d_in[iWhh0r];
    const float* bi0r  = (const float*)d_in[ibi0r];
    const float* bh0r  = (const float*)d_in[ibh0r];
    const float* Wih1f = (const float*)d_in[iWih1f];
    const float* Whh1f = (const float*)d_in[iWhh1f];
    const float* bi1f  = (const float*)d_in[ibi1f];
    const float* bh1f  = (const float*)d_in[ibh1f];
    const float* Wih1r = (const float*)d_in[iWih1r];
    const float* Whh1r = (const float*)d_in[iWhh1r];
    const float* bi1r  = (const float*)d_in[ibi1r];
    const float* bh1r  = (const float*)d_in[ibh1r];
    float* out = (float*)d_out;

    cudaFuncSetAttribute(lstm_layer, cudaFuncAttributeMaxDynamicSharedMemorySize, 131072);

    const dim3 gg(2048/64, MTOT/64);     // (32, 256)

    // ---- layer 0 ----  (8 graph nodes total this launch)
    gemm_nt<<<gg, 256>>>(X, 0, Wih0f, bi0f, bh0f, 0, 512);
    gemm_nt<<<gg, 256>>>(X, 0, Wih0r, bi0r, bh0r, 1, 512);
    init_state<<<256, 256>>>();
    lstm_layer<<<128, 256, 131072>>>(Whh0f, Whh0r, 0, out, out_size);

    // ---- layer 1 ----
    gemm_nt<<<gg, 256>>>(X, 1, Wih1f, bi1f, bh1f, 0, 1024);
    gemm_nt<<<gg, 256>>>(X, 1, Wih1r, bi1r, bh1r, 1, 1024);
    init_state<<<256, 256>>>();
    lstm_layer<<<128, 256, 131072>>>(Whh1f, Whh1r, 1, out, out_size);
}

// round 15
// speedup vs baseline: 1.0961x; 1.0961x over previous
#include <cuda_runtime.h>
#include <cuda_bf16.h>
#include <math.h>
#include <mma.h>
using namespace nvcuda;

#define HID   512
#define MTOT  16384             // 32*512 rows, m = b*512 + t
#define OUT_HID  16777216ull    // 32*512*1024
#define OUT_CELL 16842752ull
#define OUT_FULL 16908288

// W_ih plane offsets (elements)
#define OFF0F 0ull
#define OFF0R 1048576ull
#define OFF1F 2097152ull
#define OFF1R 4194304ull

// ---------------- static device scratch ----------------
__device__ __align__(16) float g_gxf[(size_t)MTOT*2048];  // fwd input projections
__device__ __align__(16) float g_gxr[(size_t)MTOT*2048];  // rev input projections
__device__ __align__(16) float g_y[(size_t)MTOT*1024];    // layer-0 output [m][2H] fp32
__device__ __align__(16) float g_h[2][2][16384];          // [parity][dir][u*32+b]
__device__ __align__(16) __nv_bfloat16 g_xt_hi[(size_t)MTOT*512];
__device__ __align__(16) __nv_bfloat16 g_xt_lo[(size_t)MTOT*512];
__device__ __align__(16) __nv_bfloat16 g_yt_hi[(size_t)MTOT*1024];
__device__ __align__(16) __nv_bfloat16 g_yt_lo[(size_t)MTOT*1024];
__device__ __align__(16) __nv_bfloat16 g_wp_hi[6291456];
__device__ __align__(16) __nv_bfloat16 g_wp_lo[6291456];
__device__ unsigned g_cnt[2];
__device__ unsigned g_gen[2];

__global__ void init_state() {
    int i = blockIdx.x*256 + threadIdx.x;
    if (i < 2*2*16384) ((float*)g_h)[i] = 0.f;
    if (i < 2) { g_cnt[i] = 0u; g_gen[i] = 0u; }
}

// split fp32 -> (hi, lo) bf16 planes.
// sel: 0 = X planes, 1 = y planes, 2 = weight pool at offset woff.
__global__ void conv_split(const float* __restrict__ src, int sel, size_t woff, int n) {
    int i = blockIdx.x*256 + threadIdx.x;
    if (i >= n) return;
    float v = (sel == 1) ? g_y[i] : src[i];
    __nv_bfloat16 hi = __float2bfloat16(v);
    __nv_bfloat16 lo = __float2bfloat16(v - __bfloat162float(hi));
    if (sel == 0)      { g_xt_hi[i] = hi;        g_xt_lo[i] = lo; }
    else if (sel == 1) { g_yt_hi[i] = hi;        g_yt_lo[i] = lo; }
    else               { g_wp_hi[woff+i] = hi;   g_wp_lo[woff+i] = lo; }
}

// ---------------- split-bf16 tensor GEMM ----------------
// C[MTOT x 2048] = A[MTOT x K] @ W[2048 x K]^T (no bias; bias added in recurrence)
// Tile 128(M) x 64(N), 256 threads = 8 warps on a 4x2 warp grid:
//   wm = (warp>>1)*32 in {0,32,64,96}  (M=128: max row 96+31=127 < 128, OK)
//   wn = (warp&1)*32  in {0,32}        (N=64:  max row 32+31=63  < 64,  OK)
__global__ __launch_bounds__(256) void gemm_bf16(
        int asel, size_t woff, int csel, int K) {
    __shared__ __align__(32) __nv_bfloat16 sA[2][128][16];
    __shared__ __align__(32) __nv_bfloat16 sB[2][64][16];
    const __nv_bfloat16* Ahi = asel ? g_yt_hi : g_xt_hi;
    const __nv_bfloat16* Alo = asel ? g_yt_lo : g_xt_lo;
    const __nv_bfloat16* Bhi = g_wp_hi + woff;
    const __nv_bfloat16* Blo = g_wp_lo + woff;
    float* C = csel ? g_gxr : g_gxf;

    const int bm = blockIdx.y*128, bn = blockIdx.x*64;
    const int tid = threadIdx.x, warp = tid >> 5;
    const int wm = (warp >> 1)*32, wn = (warp & 1)*32;

    // A loads: plane p = tid>>7, row = tid&127; two 8-elem halves per thread.
    const int pA = tid >> 7, rA = tid & 127;
    // B loads: plane p = tid>>7, row = (tid>>1)&63, half = tid&1.
    const int pB = tid >> 7, rB = (tid >> 1) & 63, hB = (tid & 1)*8;
    const __nv_bfloat16* Ap = pA ? Alo : Ahi;
    const __nv_bfloat16* Bp = pB ? Blo : Bhi;

    wmma::fragment<wmma::accumulator,16,16,16,float> acc[2][2];
#pragma unroll
    for (int i = 0; i < 2; i++)
#pragma unroll
        for (int j = 0; j < 2; j++) wmma::fill_fragment(acc[i][j], 0.f);

    for (int k0 = 0; k0 < K; k0 += 16) {
        *(uint4*)&sA[pA][rA][0] = *(const uint4*)&Ap[(size_t)(bm+rA)*K + k0];
        *(uint4*)&sA[pA][rA][8] = *(const uint4*)&Ap[(size_t)(bm+rA)*K + k0 + 8];
        *(uint4*)&sB[pB][rB][hB] = *(const uint4*)&Bp[(size_t)(bn+rB)*K + k0 + hB];
        __syncthreads();

        wmma::fragment<wmma::matrix_a,16,16,16,__nv_bfloat16,wmma::row_major> ah[2], al[2];
        wmma::fragment<wmma::matrix_b,16,16,16,__nv_bfloat16,wmma::col_major> bh[2], bl[2];
#pragma unroll
        for (int i = 0; i < 2; i++) {
            wmma::load_matrix_sync(ah[i], &sA[0][wm+16*i][0], 16);
            wmma::load_matrix_sync(al[i], &sA[1][wm+16*i][0], 16);
        }
#pragma unroll
        for (int j = 0; j < 2; j++) {
            wmma::load_matrix_sync(bh[j], &sB[0][wn+16*j][0], 16);
            wmma::load_matrix_sync(bl[j], &sB[1][wn+16*j][0], 16);
        }
#pragma unroll
        for (int i = 0; i < 2; i++)
#pragma unroll
            for (int j = 0; j < 2; j++) {
                wmma::mma_sync(acc[i][j], ah[i], bh[j], acc[i][j]);
                wmma::mma_sync(acc[i][j], ah[i], bl[j], acc[i][j]);
                wmma::mma_sync(acc[i][j], al[i], bh[j], acc[i][j]);
            }
        __syncthreads();
    }
#pragma unroll
    for (int i = 0; i < 2; i++)
#pragma unroll
        for (int j = 0; j < 2; j++)
            wmma::store_matrix_sync(&C[(size_t)(bm+wm+16*i)*2048 + bn+wn+16*j],
                                    acc[i][j], 2048, wmma::mem_row_major);
}

// ---------------- persistent bidirectional LSTM layer (validated R12) ----------------
// + bias registers (b4), since the GEMM no longer adds biases.
__global__ void __launch_bounds__(256, 1) lstm_layer(
        const float* __restrict__ Whf, const float* __restrict__ Whr,
        const float* __restrict__ bif, const float* __restrict__ bhf,
        const float* __restrict__ bir, const float* __restrict__ bhr,
        int layer, float* __restrict__ out, int out_size) {
    extern __shared__ float sm[];
    float* sW = sm;           // [32][512]
    float* sh = sm + 16384;   // [512][32]

    const int dir = blockIdx.x >> 6;
    const int u0 = (blockIdx.x & 63) * 8;
    const int tid = threadIdx.x, w = tid >> 5, b = tid & 31;
    const int u = u0 + w;
    const float* Whh = dir ? Whr : Whf;
    const float* gx  = dir ? g_gxr : g_gxf;
    const float* bi  = dir ? bir : bif;
    const float* bh  = dir ? bhr : bhf;

    for (int i = tid; i < 32*512; i += 256) {
        int ri = i >> 9, k = i & 511;
        sW[i] = Whh[(size_t)(((ri >> 3) << 9) + u0 + (ri & 7))*512 + k];
    }
    float b4[4];
#pragma unroll
    for (int g = 0; g < 4; g++) { int n = g*512 + u; b4[g] = bi[n] + bh[n]; }
    float c = 0.f;
    __syncthreads();

    for (int s = 0; s < 512; ++s) {
        const int t = dir ? (511 - s) : s;
        const int rp = s & 1, wp = rp ^ 1;

        const float4* hsrc = (const float4*)g_h[rp][dir];
        for (int i = tid; i < 4096; i += 256)
            ((float4*)sh)[i] = __ldcg(hsrc + i);
        __syncthreads();

        const size_t gb = ((size_t)b*512 + t)*2048 + u;
        float a0 = gx[gb]        + b4[0];
        float a1 = gx[gb + 512]  + b4[1];
        float a2 = gx[gb + 1024] + b4[2];
        float a3 = gx[gb + 1536] + b4[3];

        const float* r0 = sW + (size_t)( w      )*512;
        const float* r1 = sW + (size_t)( 8 + w  )*512;
        const float* r2 = sW + (size_t)(16 + w  )*512;
        const float* r3 = sW + (size_t)(24 + w  )*512;
#pragma unroll 4
        for (int k = 0; k < 512; k += 4) {
            float4 w0 = *(const float4*)(r0 + k);
            float4 w1 = *(const float4*)(r1 + k);
            float4 w2 = *(const float4*)(r2 + k);
            float4 w3 = *(const float4*)(r3 + k);
            float h0 = sh[(k+0)*32 + b];
            float h1 = sh[(k+1)*32 + b];
            float h2 = sh[(k+2)*32 + b];
            float h3 = sh[(k+3)*32 + b];
            a0 += w0.x*h0 + w0.y*h1 + w0.z*h2 + w0.w*h3;
            a1 += w1.x*h0 + w1.y*h1 + w1.z*h2 + w1.w*h3;
            a2 += w2.x*h0 + w2.y*h1 + w2.z*h2 + w2.w*h3;
            a3 += w3.x*h0 + w3.y*h1 + w3.z*h2 + w3.w*h3;
        }

        float ig = 1.f / (1.f + expf(-a0));
        float fg = 1.f / (1.f + expf(-a1));
        float gg = tanhf(a2);
        float og = 1.f / (1.f + expf(-a3));
        c = fg * c + ig * gg;
        float h = og * tanhf(c);

        g_h[wp][dir][u*32 + b] = h;

        const size_t mo = ((size_t)b*512 + t)*1024 + (size_t)dir*512 + u;
        if (layer == 0) g_y[mo] = h;
        else            out[mo]  = h;

        if (s == 511 && out_size >= OUT_FULL) {
            size_t o = (size_t)(layer*2 + dir)*16384 + (size_t)b*512 + u;
            out[OUT_HID  + o] = h;
            out[OUT_CELL + o] = c;
        }

        __threadfence();
        __syncthreads();
        if (tid == 0) {
            volatile unsigned* vg = &g_gen[dir];
            unsigned g = *vg;
            __threadfence();
            if (atomicAdd(&g_cnt[dir], 1u) == 63u) {
                atomicExch(&g_cnt[dir], 0u);
                __threadfence();
                atomicExch(&g_gen[dir], g + 1u);
            } else {
                while (*vg == g) __nanosleep(64);
            }
        }
        __syncthreads();
    }
}

// ---------------- launch ----------------
extern "C" void kernel_launch(void* const* d_in, const int* in_sizes, int n_in,
                              void* d_out, int out_size) {
    int iX, iWih0f, iWhh0f, ibi0f, ibh0f, iWih0r, iWhh0r, ibi0r, ibh0r;
    int iWih1f, iWhh1f, ibi1f, ibh1f, iWih1r, iWhh1r, ibi1r, ibh1r;
    if (n_in >= 17 && in_sizes[0] != MTOT*512 && in_sizes[8] == MTOT*512) {
        iWhh0f = 0; iWhh0r = 1; iWhh1f = 2; iWhh1r = 3;
        iWih0f = 4; iWih0r = 5; iWih1f = 6; iWih1r = 7;
        iX = 8;
        ibh0f = 9;  ibh0r = 10; ibh1f = 11; ibh1r = 12;
        ibi0f = 13; ibi0r = 14; ibi1f = 15; ibi1r = 16;
    } else {
        iX = 0;
        iWih0f = 1;  iWhh0f = 2;  ibi0f = 3;  ibh0f = 4;
        iWih0r = 5;  iWhh0r = 6;  ibi0r = 7;  ibh0r = 8;
        iWih1f = 9;  iWhh1f = 10; ibi1f = 11; ibh1f = 12;
        iWih1r = 13; iWhh1r = 14; ibi1r = 15; ibh1r = 16;
    }
    const float* X     = (const float*)d_in[iX];
    const float* Wih0f = (const float*)d_in[iWih0f];
    const float* Whh0f = (const float*)d_in[iWhh0f];
    const float* bi0f  = (const float*)d_in[ibi0f];
    const float* bh0f  = (const float*)d_in[ibh0f];
    const float* Wih0r = (const float*)d_in[iWih0r];
    const float* Whh0r = (const float*)d_in[iWhh0r];
    const float* bi0r  = (const float*)d_in[ibi0r];
    const float* bh0r  = (const float*)d_in[ibh0r];
    const float* Wih1f = (const float*)d_in[iWih1f];
    const float* Whh1f = (const float*)d_in[iWhh1f];
    const float* bi1f  = (const float*)d_in[ibi1f];
    const float* bh1f  = (const float*)d_in[ibh1f];
    const float* Wih1r = (const float*)d_in[iWih1r];
    const float* Whh1r = (const float*)d_in[iWhh1r];
    const float* bi1r  = (const float*)d_in[ibi1r];
    const float* bh1r  = (const float*)d_in[ibh1r];
    float* out = (float*)d_out;

    cudaFuncSetAttribute(lstm_layer, cudaFuncAttributeMaxDynamicSharedMemorySize, 131072);

    const dim3 gg(2048/64, MTOT/128);    // (32, 128)

    // conversions
    conv_split<<<(MTOT*512+255)/256, 256>>>(X, 0, 0, MTOT*512);
    conv_split<<<4096, 256>>>(Wih0f, 2, OFF0F, 1048576);
    conv_split<<<4096, 256>>>(Wih0r, 2, OFF0R, 1048576);
    conv_split<<<8192, 256>>>(Wih1f, 2, OFF1F, 2097152);
    conv_split<<<8192, 256>>>(Wih1r, 2, OFF1R, 2097152);

    // ---- layer 0 ----
    gemm_bf16<<<gg, 256>>>(0, OFF0F, 0, 512);
    gemm_bf16<<<gg, 256>>>(0, OFF0R, 1, 512);
    init_state<<<256, 256>>>();
    lstm_layer<<<128, 256, 131072>>>(Whh0f, Whh0r, bi0f, bh0f, bi0r, bh0r, 0, out, out_size);

    // ---- layer 1 ----
    conv_split<<<(MTOT*1024+255)/256, 256>>>(nullptr, 1, 0, MTOT*1024);
    gemm_bf16<<<gg, 256>>>(1, OFF1F, 0, 1024);
    gemm_bf16<<<gg, 256>>>(1, OFF1R, 1, 1024);
    init_state<<<256, 256>>>();
    lstm_layer<<<128, 256, 131072>>>(Whh1f, Whh1r, bi1f, bh1f, bi1r, bh1r, 1, out, out_size);
}

// round 17
// speedup vs baseline: 1.3502x; 1.2319x over previous
#include <cuda_runtime.h>
#include <cuda_bf16.h>
#include <cstdint>
#include <math.h>
#include <mma.h>
using namespace nvcuda;

#define HID   512
#define MTOT  16384             // 32*512 rows, m = b*512 + t
#define OUT_HID  16777216ull
#define OUT_CELL 16842752ull
#define OUT_FULL 16908288

#define OFF0F 0ull
#define OFF0R 1048576ull
#define OFF1F 2097152ull
#define OFF1R 4194304ull

// smem layout for lstm kernel (byte offsets; LDW in bf16 elements)
#define LDW 520                  // padded leading dim (elems) for W and H tiles
#define SM_WHI 0
#define SM_WLO 33280
#define SM_HHI 66560
#define SM_HLO 99840
#define SM_C   133120            // fp32 C staging 32x36
#define SM_TOTAL 137728

// ---------------- static device scratch ----------------
__device__ __align__(16) float g_gxf[(size_t)MTOT*2048];
__device__ __align__(16) float g_gxr[(size_t)MTOT*2048];
__device__ __align__(16) __nv_bfloat16 g_xt_hi[(size_t)MTOT*512];
__device__ __align__(16) __nv_bfloat16 g_xt_lo[(size_t)MTOT*512];
__device__ __align__(16) __nv_bfloat16 g_yt_hi[(size_t)MTOT*1024];
__device__ __align__(16) __nv_bfloat16 g_yt_lo[(size_t)MTOT*1024];
__device__ __align__(16) __nv_bfloat16 g_wp_hi[6291456];
__device__ __align__(16) __nv_bfloat16 g_wp_lo[6291456];
__device__ __align__(16) __nv_bfloat16 g_hb[2][2][2][16384];  // [parity][dir][hi|lo][b*512+u]
__device__ unsigned g_cnt[2];
__device__ unsigned g_gen[2];

__global__ void init_state() {
    int i = blockIdx.x*256 + threadIdx.x;
    if (i < 65536) ((unsigned int*)g_hb)[i] = 0u;   // 131072 bf16 zeros
    if (i < 2) { g_cnt[i] = 0u; g_gen[i] = 0u; }
}

// split fp32 -> (hi, lo) planes. sel: 0 = X planes, 2 = weight pool @ woff.
__global__ void conv_split(const float* __restrict__ src, int sel, size_t woff, int n) {
    int i = blockIdx.x*256 + threadIdx.x;
    if (i >= n) return;
    float v = src[i];
    __nv_bfloat16 hi = __float2bfloat16(v);
    __nv_bfloat16 lo = __float2bfloat16(v - __bfloat162float(hi));
    if (sel == 0) { g_xt_hi[i] = hi;      g_xt_lo[i] = lo; }
    else          { g_wp_hi[woff+i] = hi; g_wp_lo[woff+i] = lo; }
}

// ---------------- split-bf16 tensor GEMM (validated R14) ----------------
__global__ __launch_bounds__(256) void gemm_bf16(
        int asel, size_t woff, int csel, int K) {
    __shared__ __align__(32) __nv_bfloat16 sA[2][128][16];
    __shared__ __align__(32) __nv_bfloat16 sB[2][64][16];
    const __nv_bfloat16* Ahi = asel ? g_yt_hi : g_xt_hi;
    const __nv_bfloat16* Alo = asel ? g_yt_lo : g_xt_lo;
    const __nv_bfloat16* Bhi = g_wp_hi + woff;
    const __nv_bfloat16* Blo = g_wp_lo + woff;
    float* C = csel ? g_gxr : g_gxf;

    const int bm = blockIdx.y*128, bn = blockIdx.x*64;
    const int tid = threadIdx.x, warp = tid >> 5;
    const int wm = (warp >> 1)*32, wn = (warp & 1)*32;
    const int pA = tid >> 7, rA = tid & 127;
    const int pB = tid >> 7, rB = (tid >> 1) & 63, hB = (tid & 1)*8;
    const __nv_bfloat16* Ap = pA ? Alo : Ahi;
    const __nv_bfloat16* Bp = pB ? Blo : Bhi;

    wmma::fragment<wmma::accumulator,16,16,16,float> acc[2][2];
#pragma unroll
    for (int i = 0; i < 2; i++)
#pragma unroll
        for (int j = 0; j < 2; j++) wmma::fill_fragment(acc[i][j], 0.f);

    for (int k0 = 0; k0 < K; k0 += 16) {
        *(uint4*)&sA[pA][rA][0] = *(const uint4*)&Ap[(size_t)(bm+rA)*K + k0];
        *(uint4*)&sA[pA][rA][8] = *(const uint4*)&Ap[(size_t)(bm+rA)*K + k0 + 8];
        *(uint4*)&sB[pB][rB][hB] = *(const uint4*)&Bp[(size_t)(bn+rB)*K + k0 + hB];
        __syncthreads();
        wmma::fragment<wmma::matrix_a,16,16,16,__nv_bfloat16,wmma::row_major> ah[2], al[2];
        wmma::fragment<wmma::matrix_b,16,16,16,__nv_bfloat16,wmma::col_major> bh[2], bl[2];
#pragma unroll
        for (int i = 0; i < 2; i++) {
            wmma::load_matrix_sync(ah[i], &sA[0][wm+16*i][0], 16);
            wmma::load_matrix_sync(al[i], &sA[1][wm+16*i][0], 16);
        }
#pragma unroll
        for (int j = 0; j < 2; j++) {
            wmma::load_matrix_sync(bh[j], &sB[0][wn+16*j][0], 16);
            wmma::load_matrix_sync(bl[j], &sB[1][wn+16*j][0], 16);
        }
#pragma unroll
        for (int i = 0; i < 2; i++)
#pragma unroll
            for (int j = 0; j < 2; j++) {
                wmma::mma_sync(acc[i][j], ah[i], bh[j], acc[i][j]);
                wmma::mma_sync(acc[i][j], ah[i], bl[j], acc[i][j]);
                wmma::mma_sync(acc[i][j], al[i], bh[j], acc[i][j]);
            }
        __syncthreads();
    }
#pragma unroll
    for (int i = 0; i < 2; i++)
#pragma unroll
        for (int j = 0; j < 2; j++)
            wmma::store_matrix_sync(&C[(size_t)(bm+wm+16*i)*2048 + bn+wn+16*j],
                                    acc[i][j], 2048, wmma::mem_row_major);
}

// ---------------- persistent tensor-core LSTM layer ----------------
// 128 CTAs (64/dir), 128 threads each. Per step per CTA: C[32x32] = Whh_blk[32x512] @ h^T,
// via wmma split-bf16 (3 products). W in smem once; h carried as bf16 hi/lo planes.
__global__ void __launch_bounds__(128, 1) lstm_layer(
        const float* __restrict__ Whf, const float* __restrict__ Whr,
        const float* __restrict__ bif, const float* __restrict__ bhf,
        const float* __restrict__ bir, const float* __restrict__ bhr,
        int layer, float* __restrict__ out, int out_size) {
    extern __shared__ __align__(16) char sm[];
    __nv_bfloat16* sWhi = (__nv_bfloat16*)(sm + SM_WHI);
    __nv_bfloat16* sWlo = (__nv_bfloat16*)(sm + SM_WLO);
    __nv_bfloat16* sHhi = (__nv_bfloat16*)(sm + SM_HHI);
    __nv_bfloat16* sHlo = (__nv_bfloat16*)(sm + SM_HLO);
    float*         sC   = (float*)(sm + SM_C);         // [32][36]

    const int dir = blockIdx.x >> 6;
    const int u0 = (blockIdx.x & 63) * 8;
    const int tid = threadIdx.x, warp = tid >> 5, lane = tid & 31;
    const float* Whh = dir ? Whr : Whf;
    const float* gx  = dir ? g_gxr : g_gxf;
    const float* bi  = dir ? bir : bif;
    const float* bh  = dir ? bhr : bhf;

    // stage + split W_hh block rows once: row ri = g*8+u_local -> W row g*512+u0+u_local
    for (int i = tid; i < 32*512; i += 128) {
        int ri = i >> 9, k = i & 511;
        float v = Whh[(size_t)(((ri >> 3) << 9) + u0 + (ri & 7))*512 + k];
        __nv_bfloat16 hi = __float2bfloat16(v);
        sWhi[ri*LDW + k] = hi;
        sWlo[ri*LDW + k] = __float2bfloat16(v - __bfloat162float(hi));
    }
    // epilogue mapping: thread = (q = warp, b = lane); units uu = q, q+4
    const int b = lane, q = warp;
    float b4[2][4], c2[2] = {0.f, 0.f};
#pragma unroll
    for (int j = 0; j < 2; j++) {
        int ug = u0 + q + 4*j;
#pragma unroll
        for (int g = 0; g < 4; g++) { int n = g*512 + ug; b4[j][g] = bi[n] + bh[n]; }
    }
    // wmma quadrant for this warp
    const int wm = (warp & 1)*16, wn = (warp >> 1)*16;
    __syncthreads();

    for (int s = 0; s < 512; ++s) {
        const int t = dir ? (511 - s) : s;
        const int rp = s & 1, wp = rp ^ 1;

        // copy h planes (linear n*512+k) into padded smem [n*LDW+k]
        const uint4* srcHi = (const uint4*)&g_hb[rp][dir][0][0];
        const uint4* srcLo = (const uint4*)&g_hb[rp][dir][1][0];
        for (int i = tid; i < 2048; i += 128) {
            int l = i << 3;                    // element index
            int n = l >> 9, k = l & 511;
            *(uint4*)&sHhi[n*LDW + k] = __ldcg(srcHi + i);
            *(uint4*)&sHlo[n*LDW + k] = __ldcg(srcLo + i);
        }
        __syncthreads();

        wmma::fragment<wmma::accumulator,16,16,16,float> acc;
        wmma::fill_fragment(acc, 0.f);
#pragma unroll 4
        for (int kt = 0; kt < 32; ++kt) {
            const int k = kt << 4;
            wmma::fragment<wmma::matrix_a,16,16,16,__nv_bfloat16,wmma::row_major> ah, al;
            wmma::fragment<wmma::matrix_b,16,16,16,__nv_bfloat16,wmma::col_major> bhf_, blf_;
            wmma::load_matrix_sync(ah,  &sWhi[wm*LDW + k], LDW);
            wmma::load_matrix_sync(al,  &sWlo[wm*LDW + k], LDW);
            wmma::load_matrix_sync(bhf_, &sHhi[wn*LDW + k], LDW);
            wmma::load_matrix_sync(blf_, &sHlo[wn*LDW + k], LDW);
            wmma::mma_sync(acc, ah, bhf_, acc);
            wmma::mma_sync(acc, ah, blf_, acc);
            wmma::mma_sync(acc, al, bhf_, acc);
        }
        wmma::store_matrix_sync(&sC[wm*36 + wn], acc, 36, wmma::mem_row_major);
        __syncthreads();

#pragma unroll
        for (int j = 0; j < 2; j++) {
            const int uu = q + 4*j, ug = u0 + uu;
            const size_t gb = ((size_t)b*512 + t)*2048 + ug;
            float a0 = sC[( 0 + uu)*36 + b] + gx[gb]        + b4[j][0];
            float a1 = sC[( 8 + uu)*36 + b] + gx[gb + 512]  + b4[j][1];
            float a2 = sC[(16 + uu)*36 + b] + gx[gb + 1024] + b4[j][2];
            float a3 = sC[(24 + uu)*36 + b] + gx[gb + 1536] + b4[j][3];

            float ig = 1.f / (1.f + expf(-a0));
            float fg = 1.f / (1.f + expf(-a1));
            float gg = tanhf(a2);
            float og = 1.f / (1.f + expf(-a3));
            c2[j] = fg * c2[j] + ig * gg;
            float h = og * tanhf(c2[j]);

            __nv_bfloat16 hhi = __float2bfloat16(h);
            __nv_bfloat16 hlo = __float2bfloat16(h - __bfloat162float(hhi));
            const int si = b*512 + ug;
            g_hb[wp][dir][0][si] = hhi;
            g_hb[wp][dir][1][si] = hlo;

            const size_t mo = ((size_t)b*512 + t)*1024 + (size_t)dir*512 + ug;
            if (layer == 0) { g_yt_hi[mo] = hhi; g_yt_lo[mo] = hlo; }
            else            { out[mo] = h; }

            if (s == 511 && out_size >= OUT_FULL) {
                size_t o = (size_t)(layer*2 + dir)*16384 + (size_t)b*512 + ug;
                out[OUT_HID  + o] = h;
                out[OUT_CELL + o] = c2[j];
            }
        }

        __threadfence();
        __syncthreads();
        if (tid == 0) {
            volatile unsigned* vg = &g_gen[dir];
            unsigned g = *vg;
            __threadfence();
            if (atomicAdd(&g_cnt[dir], 1u) == 63u) {
                atomicExch(&g_cnt[dir], 0u);
                __threadfence();
                atomicExch(&g_gen[dir], g + 1u);
            } else {
                while (*vg == g) __nanosleep(64);
            }
        }
        __syncthreads();
    }
}

// ---------------- launch ----------------
extern "C" void kernel_launch(void* const* d_in, const int* in_sizes, int n_in,
                              void* d_out, int out_size) {
    int iX, iWih0f, iWhh0f, ibi0f, ibh0f, iWih0r, iWhh0r, ibi0r, ibh0r;
    int iWih1f, iWhh1f, ibi1f, ibh1f, iWih1r, iWhh1r, ibi1r, ibh1r;
    if (n_in >= 17 && in_sizes[0] != MTOT*512 && in_sizes[8] == MTOT*512) {
        iWhh0f = 0; iWhh0r = 1; iWhh1f = 2; iWhh1r = 3;
        iWih0f = 4; iWih0r = 5; iWih1f = 6; iWih1r = 7;
        iX = 8;
        ibh0f = 9;  ibh0r = 10; ibh1f = 11; ibh1r = 12;
        ibi0f = 13; ibi0r = 14; ibi1f = 15; ibi1r = 16;
    } else {
        iX = 0;
        iWih0f = 1;  iWhh0f = 2;  ibi0f = 3;  ibh0f = 4;
        iWih0r = 5;  iWhh0r = 6;  ibi0r = 7;  ibh0r = 8;
        iWih1f = 9;  iWhh1f = 10; ibi1f = 11; ibh1f = 12;
        iWih1r = 13; iWhh1r = 14; ibi1r = 15; ibh1r = 16;
    }
    const float* X     = (const float*)d_in[iX];
    const float* Wih0f = (const float*)d_in[iWih0f];
    const float* Whh0f = (const float*)d_in[iWhh0f];
    const float* bi0f  = (const float*)d_in[ibi0f];
    const float* bh0f  = (const float*)d_in[ibh0f];
    const float* Wih0r = (const float*)d_in[iWih0r];
    const float* Whh0r = (const float*)d_in[iWhh0r];
    const float* bi0r  = (const float*)d_in[ibi0r];
    const float* bh0r  = (const float*)d_in[ibh0r];
    const float* Wih1f = (const float*)d_in[iWih1f];
    const float* Whh1f = (const float*)d_in[iWhh1f];
    const float* bi1f  = (const float*)d_in[ibi1f];
    const float* bh1f  = (const float*)d_in[ibh1f];
    const float* Wih1r = (const float*)d_in[iWih1r];
    const float* Whh1r = (const float*)d_in[iWhh1r];
    const float* bi1r  = (const float*)d_in[ibi1r];
    const float* bh1r  = (const float*)d_in[ibh1r];
    float* out = (float*)d_out;

    cudaFuncSetAttribute(lstm_layer, cudaFuncAttributeMaxDynamicSharedMemorySize, SM_TOTAL);

    const dim3 gg(2048/64, MTOT/128);    // (32, 128)

    conv_split<<<(MTOT*512+255)/256, 256>>>(X, 0, 0, MTOT*512);
    conv_split<<<4096, 256>>>(Wih0f, 2, OFF0F, 1048576);
    conv_split<<<4096, 256>>>(Wih0r, 2, OFF0R, 1048576);
    conv_split<<<8192, 256>>>(Wih1f, 2, OFF1F, 2097152);
    conv_split<<<8192, 256>>>(Wih1r, 2, OFF1R, 2097152);

    // ---- layer 0 ----
    gemm_bf16<<<gg, 256>>>(0, OFF0F, 0, 512);
    gemm_bf16<<<gg, 256>>>(0, OFF0R, 1, 512);
    init_state<<<256, 256>>>();
    lstm_layer<<<128, 128, SM_TOTAL>>>(Whh0f, Whh0r, bi0f, bh0f, bi0r, bh0r, 0, out, out_size);

    // ---- layer 1 ---- (layer-0 recurrence wrote g_yt planes directly)
    gemm_bf16<<<gg, 256>>>(1, OFF1F, 0, 1024);
    gemm_bf16<<<gg, 256>>>(1, OFF1R, 1, 1024);
    init_state<<<256, 256>>>();
    lstm_layer<<<128, 128, SM_TOTAL>>>(Whh1f, Whh1r, bi1f, bh1f, bi1r, bh1r, 1, out, out_size);
}